// round 1
// baseline (speedup 1.0000x reference)
#include <cuda_runtime.h>
#include <math_constants.h>

// Problem constants
#define MROWS 8192      // B*S = 4*2048
#define DM    1024      // d_model
#define SLEN  2048
#define NHEAD 16
#define DK    64

// Scratch (device globals: allocation-guard safe). Head-major Q/K/V: [B*H][S][DK].
__device__ float g_Q[(size_t)MROWS * DM];
__device__ float g_K[(size_t)MROWS * DM];
__device__ float g_V[(size_t)MROWS * DM];
__device__ float g_O[(size_t)MROWS * DM];   // attention output, [B,S,D] row-major

// ---------------------------------------------------------------------------
// GEMM: C = A[8192x1024] @ W[1024x1024], 128x128 block tile, 8x8 per thread.
// MODE 0: +0.1*sin, scatter to head-major (Q)
// MODE 1: +0.1*cos, scatter to head-major (K)
// MODE 2: +alpha*0.1*tanh, scatter to head-major (V)
// MODE 3: plain, row-major write (output projection)
// ---------------------------------------------------------------------------
template<int MODE>
__global__ __launch_bounds__(256, 2)
void gemm_k(const float* __restrict__ A, const float* __restrict__ W,
            float* __restrict__ C, const float* __restrict__ alphap)
{
    __shared__ float As[16][128];   // As[k][m]
    __shared__ float Bs[16][128];   // Bs[k][n]

    const int tid = threadIdx.x;
    const int tx = tid & 15, ty = tid >> 4;
    const int m0 = blockIdx.y << 7;
    const int n0 = blockIdx.x << 7;

    float acc[8][8];
#pragma unroll
    for (int i = 0; i < 8; i++)
#pragma unroll
        for (int j = 0; j < 8; j++) acc[i][j] = 0.f;

    for (int k0 = 0; k0 < DM; k0 += 16) {
#pragma unroll
        for (int it = 0; it < 2; it++) {
            int idx = tid + (it << 8);
            // A tile: 128 rows x 16 k
            int ar = idx >> 2, ac = (idx & 3) << 2;
            float4 av = *(const float4*)(A + (size_t)(m0 + ar) * DM + k0 + ac);
            As[ac + 0][ar] = av.x;
            As[ac + 1][ar] = av.y;
            As[ac + 2][ar] = av.z;
            As[ac + 3][ar] = av.w;
            // B tile: 16 k x 128 cols
            int br = idx >> 5, bc = (idx & 31) << 2;
            *(float4*)(&Bs[br][bc]) =
                *(const float4*)(W + (size_t)(k0 + br) * DM + n0 + bc);
        }
        __syncthreads();

#pragma unroll
        for (int kk = 0; kk < 16; kk++) {
            float a[8], b[8];
            *(float4*)(a)     = *(const float4*)(&As[kk][ty << 2]);
            *(float4*)(a + 4) = *(const float4*)(&As[kk][64 + (ty << 2)]);
            *(float4*)(b)     = *(const float4*)(&Bs[kk][tx << 2]);
            *(float4*)(b + 4) = *(const float4*)(&Bs[kk][64 + (tx << 2)]);
#pragma unroll
            for (int i = 0; i < 8; i++)
#pragma unroll
                for (int j = 0; j < 8; j++)
                    acc[i][j] = fmaf(a[i], b[j], acc[i][j]);
        }
        __syncthreads();
    }

    float alpha = 0.f;
    if (MODE == 2) alpha = __ldg(alphap);

#pragma unroll
    for (int ih = 0; ih < 2; ih++)
#pragma unroll
    for (int i = 0; i < 4; i++) {
        const int m = m0 + (ih << 6) + (ty << 2) + i;
#pragma unroll
        for (int jh = 0; jh < 2; jh++) {
            const int n = n0 + (jh << 6) + (tx << 2);
            float4 v;
            v.x = acc[ih * 4 + i][jh * 4 + 0];
            v.y = acc[ih * 4 + i][jh * 4 + 1];
            v.z = acc[ih * 4 + i][jh * 4 + 2];
            v.w = acc[ih * 4 + i][jh * 4 + 3];
            if (MODE == 0) {
                v.x += 0.1f * sinf(v.x);
                v.y += 0.1f * sinf(v.y);
                v.z += 0.1f * sinf(v.z);
                v.w += 0.1f * sinf(v.w);
            } else if (MODE == 1) {
                v.x += 0.1f * cosf(v.x);
                v.y += 0.1f * cosf(v.y);
                v.z += 0.1f * cosf(v.z);
                v.w += 0.1f * cosf(v.w);
            } else if (MODE == 2) {
                const float a01 = alpha * 0.1f;
                v.x += a01 * tanhf(v.x);
                v.y += a01 * tanhf(v.y);
                v.z += a01 * tanhf(v.z);
                v.w += a01 * tanhf(v.w);
            }
            size_t dst;
            if (MODE == 3) {
                dst = (size_t)m * DM + n;
            } else {
                const int b = m >> 11;          // S = 2048
                const int s = m & 2047;
                const int h = n >> 6;           // DK = 64
                const int d = n & 63;
                dst = ((size_t)((b << 4) + h) << 17) + ((size_t)s << 6) + d;
            }
            *(float4*)(C + dst) = v;
        }
    }
}

// ---------------------------------------------------------------------------
// Flash attention: one block handles 64 query rows of one (b,h).
// smem: Qt (d-major Q), KPt (d-major K, reused as transposed P), Vs.
// 256 threads = 16x16; each thread owns a 4x4 score/output microtile.
// Row-group of 16 threads shares a half-warp -> shfl-based softmax reduce.
// ---------------------------------------------------------------------------
__global__ __launch_bounds__(256, 2)
void attn_k()
{
    __shared__ float Qt[64][64];    // Qt[d][r]
    __shared__ float KPt[64][64];   // Kt[d][c], later Pt[c][r]
    __shared__ float Vs[64][64];    // V[c][d]

    const int tid = threadIdx.x;
    const int tx = tid & 15, ty = tid >> 4;
    const int qb = blockIdx.x;      // 0..31
    const int bh = blockIdx.y;      // 0..63

    const float* __restrict__ Qp = g_Q + ((size_t)bh << 17) + ((size_t)qb << 12);
    const float* __restrict__ Kp = g_K + ((size_t)bh << 17);
    const float* __restrict__ Vp = g_V + ((size_t)bh << 17);

    // Load Q tile transposed
    {
        const int r = tid & 63, dB = (tid >> 6) << 4;
#pragma unroll
        for (int q = 0; q < 4; q++) {
            float4 v = *(const float4*)(Qp + r * DK + dB + (q << 2));
            Qt[dB + (q << 2) + 0][r] = v.x;
            Qt[dB + (q << 2) + 1][r] = v.y;
            Qt[dB + (q << 2) + 2][r] = v.z;
            Qt[dB + (q << 2) + 3][r] = v.w;
        }
    }

    float o[4][4];
#pragma unroll
    for (int i = 0; i < 4; i++)
#pragma unroll
        for (int j = 0; j < 4; j++) o[i][j] = 0.f;
    float m_r[4] = { -CUDART_INF_F, -CUDART_INF_F, -CUDART_INF_F, -CUDART_INF_F };
    float l_r[4] = { 0.f, 0.f, 0.f, 0.f };

    for (int kb = 0; kb < 32; kb++) {
        __syncthreads();   // protect KPt(P)/Vs from previous iteration readers
        {
            const int c = tid & 63, dB = (tid >> 6) << 4;
            const float* kp = Kp + ((size_t)((kb << 6) + c)) * DK + dB;
#pragma unroll
            for (int q = 0; q < 4; q++) {
                float4 v = *(const float4*)(kp + (q << 2));
                KPt[dB + (q << 2) + 0][c] = v.x;
                KPt[dB + (q << 2) + 1][c] = v.y;
                KPt[dB + (q << 2) + 2][c] = v.z;
                KPt[dB + (q << 2) + 3][c] = v.w;
            }
            const int vr = tid >> 2, vc = (tid & 3) << 4;
            const float* vp = Vp + ((size_t)((kb << 6) + vr)) * DK + vc;
#pragma unroll
            for (int q = 0; q < 4; q++)
                *(float4*)(&Vs[vr][vc + (q << 2)]) = *(const float4*)(vp + (q << 2));
        }
        __syncthreads();

        // Phase A: S = Q @ K^T (both d-major in smem)
        float s[4][4];
#pragma unroll
        for (int i = 0; i < 4; i++)
#pragma unroll
            for (int j = 0; j < 4; j++) s[i][j] = 0.f;
#pragma unroll
        for (int kk = 0; kk < 64; kk++) {
            float4 qv = *(const float4*)(&Qt[kk][ty << 2]);
            float4 kv = *(const float4*)(&KPt[kk][tx << 2]);
            const float qa[4] = { qv.x, qv.y, qv.z, qv.w };
            const float ka[4] = { kv.x, kv.y, kv.z, kv.w };
#pragma unroll
            for (int i = 0; i < 4; i++)
#pragma unroll
                for (int j = 0; j < 4; j++)
                    s[i][j] = fmaf(qa[i], ka[j], s[i][j]);
        }

        // Online softmax (per-row reduce across the 16-thread row group)
#pragma unroll
        for (int i = 0; i < 4; i++) {
#pragma unroll
            for (int j = 0; j < 4; j++) s[i][j] *= 0.125f;   // 1/sqrt(64)
            float rmax = fmaxf(fmaxf(s[i][0], s[i][1]), fmaxf(s[i][2], s[i][3]));
#pragma unroll
            for (int off = 8; off; off >>= 1)
                rmax = fmaxf(rmax, __shfl_xor_sync(0xffffffffu, rmax, off, 16));
            const float mnew = fmaxf(m_r[i], rmax);
            const float fac = __expf(m_r[i] - mnew);
            m_r[i] = mnew;
            float ps = 0.f;
#pragma unroll
            for (int j = 0; j < 4; j++) {
                s[i][j] = __expf(s[i][j] - mnew);
                ps += s[i][j];
            }
#pragma unroll
            for (int off = 8; off; off >>= 1)
                ps += __shfl_xor_sync(0xffffffffu, ps, off, 16);
            l_r[i] = l_r[i] * fac + ps;
#pragma unroll
            for (int j = 0; j < 4; j++) o[i][j] *= fac;
        }

        __syncthreads();   // all phase-A reads of KPt done
        // Store P transposed into KPt: Pt[c][r]
#pragma unroll
        for (int j = 0; j < 4; j++) {
            float4 pv = make_float4(s[0][j], s[1][j], s[2][j], s[3][j]);
            *(float4*)(&KPt[(tx << 2) + j][ty << 2]) = pv;
        }
        __syncthreads();

        // Phase C: O += P @ V
#pragma unroll
        for (int cc = 0; cc < 64; cc++) {
            float4 pv = *(const float4*)(&KPt[cc][ty << 2]);
            float4 vv = *(const float4*)(&Vs[cc][tx << 2]);
            const float pa[4] = { pv.x, pv.y, pv.z, pv.w };
            const float va[4] = { vv.x, vv.y, vv.z, vv.w };
#pragma unroll
            for (int i = 0; i < 4; i++)
#pragma unroll
                for (int j = 0; j < 4; j++)
                    o[i][j] = fmaf(pa[i], va[j], o[i][j]);
        }
    }

    // Finalize and write to [B,S,D] row-major scratch
    const int b = bh >> 4, h = bh & 15;
#pragma unroll
    for (int i = 0; i < 4; i++) {
        const float inv = 1.f / l_r[i];
        const int srow = (qb << 6) + (ty << 2) + i;
        const size_t base = ((size_t)((b << 11) + srow) << 10) + (h << 6) + (tx << 2);
        float4 ov = make_float4(o[i][0] * inv, o[i][1] * inv, o[i][2] * inv, o[i][3] * inv);
        *(float4*)(g_O + base) = ov;
    }
}

// ---------------------------------------------------------------------------
extern "C" void kernel_launch(void* const* d_in, const int* in_sizes, int n_in,
                              void* d_out, int out_size)
{
    const float* x  = (const float*)d_in[0];
    const float* Wq = (const float*)d_in[1];
    const float* Wk = (const float*)d_in[2];
    const float* Wv = (const float*)d_in[3];
    const float* Wo = (const float*)d_in[4];
    const float* al = (const float*)d_in[5];
    float* out = (float*)d_out;

    float *qp, *kp, *vp, *op;
    cudaGetSymbolAddress((void**)&qp, g_Q);
    cudaGetSymbolAddress((void**)&kp, g_K);
    cudaGetSymbolAddress((void**)&vp, g_V);
    cudaGetSymbolAddress((void**)&op, g_O);

    dim3 ggrid(DM / 128, MROWS / 128);   // 8 x 64
    gemm_k<0><<<ggrid, 256>>>(x, Wq, qp, nullptr);
    gemm_k<1><<<ggrid, 256>>>(x, Wk, kp, nullptr);
    gemm_k<2><<<ggrid, 256>>>(x, Wv, vp, al);

    attn_k<<<dim3(SLEN / 64, (MROWS / SLEN) * NHEAD), 256>>>();  // 32 x 64

    gemm_k<3><<<ggrid, 256>>>(op, Wo, out, nullptr);
}

// round 3
// speedup vs baseline: 1.0054x; 1.0054x over previous
#include <cuda_runtime.h>
#include <math_constants.h>
#include <cstdint>

// Problem constants
#define MROWS 8192      // B*S = 4*2048
#define DM    1024      // d_model
#define SLEN  2048
#define NHEAD 16
#define DK    64
#define KC    32        // K-chunk per smem stage

// Scratch (device globals). Head-major Q/K/V: [B*H][S][DK].
__device__ float g_Q[(size_t)MROWS * DM];
__device__ float g_K[(size_t)MROWS * DM];
__device__ float g_V[(size_t)MROWS * DM];
__device__ float g_O[(size_t)MROWS * DM];   // attention output, [B,S,D] row-major

// ---------------------------------------------------------------------------
// mma.sync tf32 (family-portable; works on plain sm_100 target)
// ---------------------------------------------------------------------------
__device__ __forceinline__ uint32_t f2tf32(float f) {
    uint32_t r;
    asm("cvt.rna.tf32.f32 %0, %1;" : "=r"(r) : "f"(f));
    return r;
}

__device__ __forceinline__ void mma8(float c[4], const uint32_t a[4], const uint32_t b[2]) {
    asm volatile(
        "mma.sync.aligned.m16n8k8.row.col.f32.tf32.tf32.f32 "
        "{%0,%1,%2,%3}, {%4,%5,%6,%7}, {%8,%9}, {%0,%1,%2,%3};"
        : "+f"(c[0]), "+f"(c[1]), "+f"(c[2]), "+f"(c[3])
        : "r"(a[0]), "r"(a[1]), "r"(a[2]), "r"(a[3]), "r"(b[0]), "r"(b[1]));
}

// Fragment-order smem layouts (fp32, hi/lo split derived at load time):
//  A: group g = tm_global*4 + ks  (tm_global 0..7, ks 0..3), 132 floats/group (128+4 pad)
//     element index within group = l*4 + j,  l = ((row&7)<<2)|(k&3),
//     j = ((k&4)>>1)|((row&8)>>3)
//  B: group g = tn_global*4 + ks  (tn_global 0..15), 66 floats/group (64+2 pad)
//     element = l*2 + j,  l = ((n&7)<<2)|(k&3),  j = (k&4)>>2
#define A_G 132
#define B_G 66

// ---------------------------------------------------------------------------
// 3xTF32 GEMM: C = A[8192x1024] @ W[1024x1024]
// CTA 128x128, 8 warps (2m x 4n), warp tile 64x32, KC=32.
// MODE 0: +0.1*sin -> head-major; 1: +0.1*cos -> head-major;
// MODE 2: +alpha*0.1*tanh -> head-major; 3: plain -> row-major.
// ---------------------------------------------------------------------------
template<int MODE>
__global__ __launch_bounds__(256)
void gemm_mma(const float* __restrict__ A, const float* __restrict__ W,
              float* __restrict__ C, const float* __restrict__ alphap)
{
    __shared__ float sA[32 * A_G];   // 4224 floats
    __shared__ float sB[64 * B_G];   // 4224 floats

    const int tid = threadIdx.x;
    const int lane = tid & 31;
    const int wid = tid >> 5;
    const int warpM = wid & 1;       // 0..1 (64 rows each)
    const int warpN = wid >> 1;      // 0..3 (32 cols each)
    const int m0 = blockIdx.y << 7;
    const int n0 = blockIdx.x << 7;

    float c[4][4][4];
#pragma unroll
    for (int i = 0; i < 4; i++)
#pragma unroll
        for (int j = 0; j < 4; j++)
#pragma unroll
            for (int k = 0; k < 4; k++) c[i][j][k] = 0.f;

    float4 ar[4], br[4];

    // ---- gmem load of one chunk into regs ----
    auto gload = [&](int kb) {
        const float* Ap = A + (size_t)m0 * DM + kb * KC;
        const float* Wp = W + (size_t)kb * KC * DM + n0;
#pragma unroll
        for (int it = 0; it < 4; it++) {
            const int id = tid + (it << 8);
            ar[it] = *(const float4*)(Ap + (size_t)(id >> 3) * DM + ((id & 7) << 2));
            br[it] = *(const float4*)(Wp + (size_t)(id >> 5) * DM + ((id & 31) << 2));
        }
    };

    // ---- scatter regs into fragment-order smem ----
    auto sstore = [&]() {
#pragma unroll
        for (int it = 0; it < 4; it++) {
            const int id = tid + (it << 8);
            // A: row-major float4 along k
            {
                const int row = id >> 3, k0 = (id & 7) << 2;
                const float va[4] = { ar[it].x, ar[it].y, ar[it].z, ar[it].w };
#pragma unroll
                for (int e = 0; e < 4; e++) {
                    const int k = k0 + e;
                    const int g = ((row >> 4) << 2) + (k >> 3);
                    const int l = ((row & 7) << 2) | (k & 3);
                    const int j = ((k & 4) >> 1) | ((row & 8) >> 3);
                    sA[g * A_G + (l << 2) + j] = va[e];
                }
            }
            // B: row-major float4 along n (row = k)
            {
                const int kk = id >> 5, nq = id & 31;
                const float vb[4] = { br[it].x, br[it].y, br[it].z, br[it].w };
#pragma unroll
                for (int e = 0; e < 4; e++) {
                    const int n = (nq << 2) + e;
                    const int g = ((n >> 3) << 2) + (kk >> 3);
                    const int l = ((n & 7) << 2) | (kk & 3);
                    const int j = (kk & 4) >> 2;
                    sB[g * B_G + (l << 1) + j] = vb[e];
                }
            }
        }
    };

    // ---- one chunk of mma (4 k8-steps), 3xTF32 ----
    auto compute = [&]() {
#pragma unroll
        for (int ks = 0; ks < 4; ks++) {
            uint32_t ahi[4][4], alo[4][4];
#pragma unroll
            for (int tm = 0; tm < 4; tm++) {
                const int g = (((warpM << 2) + tm) << 2) + ks;
                const float4 v = *(const float4*)&sA[g * A_G + (lane << 2)];
                const float va[4] = { v.x, v.y, v.z, v.w };
#pragma unroll
                for (int j = 0; j < 4; j++) {
                    ahi[tm][j] = f2tf32(va[j]);
                    alo[tm][j] = f2tf32(va[j] - __uint_as_float(ahi[tm][j]));
                }
            }
            uint32_t bhi[4][2], blo[4][2];
#pragma unroll
            for (int tn = 0; tn < 4; tn++) {
                const int g = (((warpN << 2) + tn) << 2) + ks;
                const float2 v = *(const float2*)&sB[g * B_G + (lane << 1)];
                const float vb[2] = { v.x, v.y };
#pragma unroll
                for (int j = 0; j < 2; j++) {
                    bhi[tn][j] = f2tf32(vb[j]);
                    blo[tn][j] = f2tf32(vb[j] - __uint_as_float(bhi[tn][j]));
                }
            }
#pragma unroll
            for (int tm = 0; tm < 4; tm++)
#pragma unroll
                for (int tn = 0; tn < 4; tn++) {
                    mma8(c[tm][tn], ahi[tm], bhi[tn]);
                    mma8(c[tm][tn], ahi[tm], blo[tn]);
                    mma8(c[tm][tn], alo[tm], bhi[tn]);
                }
        }
    };

    // ---- pipeline ----
    gload(0);
    sstore();
    __syncthreads();

    for (int kb = 0; kb < DM / KC; kb++) {
        if (kb < DM / KC - 1) gload(kb + 1);
        compute();
        __syncthreads();
        if (kb < DM / KC - 1) {
            sstore();
            __syncthreads();
        }
    }

    // ---- epilogue ----
    float alpha01 = 0.f;
    if (MODE == 2) alpha01 = __ldg(alphap) * 0.1f;

    auto xform = [&](float t) -> float {
        if (MODE == 0)      return t + 0.1f * sinf(t);
        else if (MODE == 1) return t + 0.1f * cosf(t);
        else if (MODE == 2) return t + alpha01 * tanhf(t);
        return t;
    };

#pragma unroll
    for (int tm = 0; tm < 4; tm++)
#pragma unroll
        for (int tn = 0; tn < 4; tn++) {
            const int row = m0 + (warpM << 6) + (tm << 4) + (lane >> 2);
            const int col = n0 + (warpN << 5) + (tn << 3) + ((lane & 3) << 1);
#pragma unroll
            for (int half = 0; half < 2; half++) {
                const int r = row + (half << 3);
                float2 v;
                v.x = xform(c[tm][tn][half * 2 + 0]);
                v.y = xform(c[tm][tn][half * 2 + 1]);
                size_t dst;
                if (MODE == 3) {
                    dst = (size_t)r * DM + col;
                } else {
                    const int b = r >> 11, s = r & 2047;
                    const int h = col >> 6, d = col & 63;
                    dst = (((size_t)((b << 4) + h)) << 17) + ((size_t)s << 6) + d;
                }
                *(float2*)(C + dst) = v;
            }
        }
}

// ---------------------------------------------------------------------------
// Flash attention (round-1 FFMA version, unchanged)
// ---------------------------------------------------------------------------
__global__ __launch_bounds__(256, 2)
void attn_k()
{
    __shared__ float Qt[64][64];
    __shared__ float KPt[64][64];
    __shared__ float Vs[64][64];

    const int tid = threadIdx.x;
    const int tx = tid & 15, ty = tid >> 4;
    const int qb = blockIdx.x;
    const int bh = blockIdx.y;

    const float* __restrict__ Qp = g_Q + ((size_t)bh << 17) + ((size_t)qb << 12);
    const float* __restrict__ Kp = g_K + ((size_t)bh << 17);
    const float* __restrict__ Vp = g_V + ((size_t)bh << 17);

    {
        const int r = tid & 63, dB = (tid >> 6) << 4;
#pragma unroll
        for (int q = 0; q < 4; q++) {
            float4 v = *(const float4*)(Qp + r * DK + dB + (q << 2));
            Qt[dB + (q << 2) + 0][r] = v.x;
            Qt[dB + (q << 2) + 1][r] = v.y;
            Qt[dB + (q << 2) + 2][r] = v.z;
            Qt[dB + (q << 2) + 3][r] = v.w;
        }
    }

    float o[4][4];
#pragma unroll
    for (int i = 0; i < 4; i++)
#pragma unroll
        for (int j = 0; j < 4; j++) o[i][j] = 0.f;
    float m_r[4] = { -CUDART_INF_F, -CUDART_INF_F, -CUDART_INF_F, -CUDART_INF_F };
    float l_r[4] = { 0.f, 0.f, 0.f, 0.f };

    for (int kb = 0; kb < 32; kb++) {
        __syncthreads();
        {
            const int c = tid & 63, dB = (tid >> 6) << 4;
            const float* kp = Kp + ((size_t)((kb << 6) + c)) * DK + dB;
#pragma unroll
            for (int q = 0; q < 4; q++) {
                float4 v = *(const float4*)(kp + (q << 2));
                KPt[dB + (q << 2) + 0][c] = v.x;
                KPt[dB + (q << 2) + 1][c] = v.y;
                KPt[dB + (q << 2) + 2][c] = v.z;
                KPt[dB + (q << 2) + 3][c] = v.w;
            }
            const int vr = tid >> 2, vc = (tid & 3) << 4;
            const float* vp = Vp + ((size_t)((kb << 6) + vr)) * DK + vc;
#pragma unroll
            for (int q = 0; q < 4; q++)
                *(float4*)(&Vs[vr][vc + (q << 2)]) = *(const float4*)(vp + (q << 2));
        }
        __syncthreads();

        float s[4][4];
#pragma unroll
        for (int i = 0; i < 4; i++)
#pragma unroll
            for (int j = 0; j < 4; j++) s[i][j] = 0.f;
#pragma unroll
        for (int kk = 0; kk < 64; kk++) {
            float4 qv = *(const float4*)(&Qt[kk][ty << 2]);
            float4 kv = *(const float4*)(&KPt[kk][tx << 2]);
            const float qa[4] = { qv.x, qv.y, qv.z, qv.w };
            const float ka[4] = { kv.x, kv.y, kv.z, kv.w };
#pragma unroll
            for (int i = 0; i < 4; i++)
#pragma unroll
                for (int j = 0; j < 4; j++)
                    s[i][j] = fmaf(qa[i], ka[j], s[i][j]);
        }

#pragma unroll
        for (int i = 0; i < 4; i++) {
#pragma unroll
            for (int j = 0; j < 4; j++) s[i][j] *= 0.125f;
            float rmax = fmaxf(fmaxf(s[i][0], s[i][1]), fmaxf(s[i][2], s[i][3]));
#pragma unroll
            for (int off = 8; off; off >>= 1)
                rmax = fmaxf(rmax, __shfl_xor_sync(0xffffffffu, rmax, off, 16));
            const float mnew = fmaxf(m_r[i], rmax);
            const float fac = __expf(m_r[i] - mnew);
            m_r[i] = mnew;
            float ps = 0.f;
#pragma unroll
            for (int j = 0; j < 4; j++) {
                s[i][j] = __expf(s[i][j] - mnew);
                ps += s[i][j];
            }
#pragma unroll
            for (int off = 8; off; off >>= 1)
                ps += __shfl_xor_sync(0xffffffffu, ps, off, 16);
            l_r[i] = l_r[i] * fac + ps;
#pragma unroll
            for (int j = 0; j < 4; j++) o[i][j] *= fac;
        }

        __syncthreads();
#pragma unroll
        for (int j = 0; j < 4; j++) {
            float4 pv = make_float4(s[0][j], s[1][j], s[2][j], s[3][j]);
            *(float4*)(&KPt[(tx << 2) + j][ty << 2]) = pv;
        }
        __syncthreads();

#pragma unroll
        for (int cc = 0; cc < 64; cc++) {
            float4 pv = *(const float4*)(&KPt[cc][ty << 2]);
            float4 vv = *(const float4*)(&Vs[cc][tx << 2]);
            const float pa[4] = { pv.x, pv.y, pv.z, pv.w };
            const float va[4] = { vv.x, vv.y, vv.z, vv.w };
#pragma unroll
            for (int i = 0; i < 4; i++)
#pragma unroll
                for (int j = 0; j < 4; j++)
                    o[i][j] = fmaf(pa[i], va[j], o[i][j]);
        }
    }

    const int b = bh >> 4, h = bh & 15;
#pragma unroll
    for (int i = 0; i < 4; i++) {
        const float inv = 1.f / l_r[i];
        const int srow = (qb << 6) + (ty << 2) + i;
        const size_t base = ((size_t)((b << 11) + srow) << 10) + (h << 6) + (tx << 2);
        float4 ov = make_float4(o[i][0] * inv, o[i][1] * inv, o[i][2] * inv, o[i][3] * inv);
        *(float4*)(g_O + base) = ov;
    }
}

// ---------------------------------------------------------------------------
extern "C" void kernel_launch(void* const* d_in, const int* in_sizes, int n_in,
                              void* d_out, int out_size)
{
    const float* x  = (const float*)d_in[0];
    const float* Wq = (const float*)d_in[1];
    const float* Wk = (const float*)d_in[2];
    const float* Wv = (const float*)d_in[3];
    const float* Wo = (const float*)d_in[4];
    const float* al = (const float*)d_in[5];
    float* out = (float*)d_out;

    float *qp, *kp, *vp, *op;
    cudaGetSymbolAddress((void**)&qp, g_Q);
    cudaGetSymbolAddress((void**)&kp, g_K);
    cudaGetSymbolAddress((void**)&vp, g_V);
    cudaGetSymbolAddress((void**)&op, g_O);

    dim3 ggrid(DM / 128, MROWS / 128);   // 8 x 64
    gemm_mma<0><<<ggrid, 256>>>(x, Wq, qp, nullptr);
    gemm_mma<1><<<ggrid, 256>>>(x, Wk, kp, nullptr);
    gemm_mma<2><<<ggrid, 256>>>(x, Wv, vp, al);

    attn_k<<<dim3(SLEN / 64, (MROWS / SLEN) * NHEAD), 256>>>();  // 32 x 64

    gemm_mma<3><<<ggrid, 256>>>(op, Wo, out, nullptr);
}

// round 4
// speedup vs baseline: 1.0675x; 1.0617x over previous
#include <cuda_runtime.h>
#include <math_constants.h>
#include <cstdint>

// Problem constants
#define MROWS 8192      // B*S = 4*2048
#define DM    1024      // d_model
#define SLEN  2048
#define NHEAD 16
#define DK    64
#define KC    32        // K-chunk per smem stage (gemm)

// Scratch (device globals). Head-major Q/K/V: [B*H][S][DK].
__device__ float g_Q[(size_t)MROWS * DM];
__device__ float g_K[(size_t)MROWS * DM];
__device__ float g_V[(size_t)MROWS * DM];
__device__ float g_O[(size_t)MROWS * DM];   // attention output, [B,S,D] row-major

// ---------------------------------------------------------------------------
// Common helpers
// ---------------------------------------------------------------------------
__device__ __forceinline__ uint32_t f2tf32(float f) {
    uint32_t r;
    asm("cvt.rna.tf32.f32 %0, %1;" : "=r"(r) : "f"(f));
    return r;
}

__device__ __forceinline__ void mma8(float c[4], const uint32_t a[4], const uint32_t b[2]) {
    asm volatile(
        "mma.sync.aligned.m16n8k8.row.col.f32.tf32.tf32.f32 "
        "{%0,%1,%2,%3}, {%4,%5,%6,%7}, {%8,%9}, {%0,%1,%2,%3};"
        : "+f"(c[0]), "+f"(c[1]), "+f"(c[2]), "+f"(c[3])
        : "r"(a[0]), "r"(a[1]), "r"(a[2]), "r"(a[3]), "r"(b[0]), "r"(b[1]));
}

// exp(x) for x <= 0 on the FMA pipe (no MUFU). |rel err| ~1e-7.
__device__ __forceinline__ float expf_poly(float x) {
    x = fmaxf(x, -87.0f);
    float y = x * 1.4426950408889634f;       // log2(e)
    int   n = __float2int_rn(y);
    float f = y - (float)n;
    float r = 1.5403530e-4f;                 // 2^f Taylor (ln2^k/k!)
    r = fmaf(r, f, 1.3333558e-3f);
    r = fmaf(r, f, 9.6181291e-3f);
    r = fmaf(r, f, 5.5504109e-2f);
    r = fmaf(r, f, 2.4022651e-1f);
    r = fmaf(r, f, 6.9314718e-1f);
    r = fmaf(r, f, 1.0f);
    return r * __int_as_float((n + 127) << 23);
}

// ---------------------------------------------------------------------------
// 3xTF32 GEMM (unchanged from round 3; ~415us each, to be revisited)
// ---------------------------------------------------------------------------
#define A_G 132
#define B_G 66

template<int MODE>
__global__ __launch_bounds__(256)
void gemm_mma(const float* __restrict__ A, const float* __restrict__ W,
              float* __restrict__ C, const float* __restrict__ alphap)
{
    __shared__ float sA[32 * A_G];
    __shared__ float sB[64 * B_G];

    const int tid = threadIdx.x;
    const int lane = tid & 31;
    const int wid = tid >> 5;
    const int warpM = wid & 1;
    const int warpN = wid >> 1;
    const int m0 = blockIdx.y << 7;
    const int n0 = blockIdx.x << 7;

    float c[4][4][4];
#pragma unroll
    for (int i = 0; i < 4; i++)
#pragma unroll
        for (int j = 0; j < 4; j++)
#pragma unroll
            for (int k = 0; k < 4; k++) c[i][j][k] = 0.f;

    float4 ar[4], br[4];

    auto gload = [&](int kb) {
        const float* Ap = A + (size_t)m0 * DM + kb * KC;
        const float* Wp = W + (size_t)kb * KC * DM + n0;
#pragma unroll
        for (int it = 0; it < 4; it++) {
            const int id = tid + (it << 8);
            ar[it] = *(const float4*)(Ap + (size_t)(id >> 3) * DM + ((id & 7) << 2));
            br[it] = *(const float4*)(Wp + (size_t)(id >> 5) * DM + ((id & 31) << 2));
        }
    };

    auto sstore = [&]() {
#pragma unroll
        for (int it = 0; it < 4; it++) {
            const int id = tid + (it << 8);
            {
                const int row = id >> 3, k0 = (id & 7) << 2;
                const float va[4] = { ar[it].x, ar[it].y, ar[it].z, ar[it].w };
#pragma unroll
                for (int e = 0; e < 4; e++) {
                    const int k = k0 + e;
                    const int g = ((row >> 4) << 2) + (k >> 3);
                    const int l = ((row & 7) << 2) | (k & 3);
                    const int j = ((k & 4) >> 1) | ((row & 8) >> 3);
                    sA[g * A_G + (l << 2) + j] = va[e];
                }
            }
            {
                const int kk = id >> 5, nq = id & 31;
                const float vb[4] = { br[it].x, br[it].y, br[it].z, br[it].w };
#pragma unroll
                for (int e = 0; e < 4; e++) {
                    const int n = (nq << 2) + e;
                    const int g = ((n >> 3) << 2) + (kk >> 3);
                    const int l = ((n & 7) << 2) | (kk & 3);
                    const int j = (kk & 4) >> 2;
                    sB[g * B_G + (l << 1) + j] = vb[e];
                }
            }
        }
    };

    auto compute = [&]() {
#pragma unroll
        for (int ks = 0; ks < 4; ks++) {
            uint32_t ahi[4][4], alo[4][4];
#pragma unroll
            for (int tm = 0; tm < 4; tm++) {
                const int g = (((warpM << 2) + tm) << 2) + ks;
                const float4 v = *(const float4*)&sA[g * A_G + (lane << 2)];
                const float va[4] = { v.x, v.y, v.z, v.w };
#pragma unroll
                for (int j = 0; j < 4; j++) {
                    ahi[tm][j] = f2tf32(va[j]);
                    alo[tm][j] = f2tf32(va[j] - __uint_as_float(ahi[tm][j]));
                }
            }
            uint32_t bhi[4][2], blo[4][2];
#pragma unroll
            for (int tn = 0; tn < 4; tn++) {
                const int g = (((warpN << 2) + tn) << 2) + ks;
                const float2 v = *(const float2*)&sB[g * B_G + (lane << 1)];
                const float vb[2] = { v.x, v.y };
#pragma unroll
                for (int j = 0; j < 2; j++) {
                    bhi[tn][j] = f2tf32(vb[j]);
                    blo[tn][j] = f2tf32(vb[j] - __uint_as_float(bhi[tn][j]));
                }
            }
#pragma unroll
            for (int tm = 0; tm < 4; tm++)
#pragma unroll
                for (int tn = 0; tn < 4; tn++) {
                    mma8(c[tm][tn], ahi[tm], bhi[tn]);
                    mma8(c[tm][tn], ahi[tm], blo[tn]);
                    mma8(c[tm][tn], alo[tm], bhi[tn]);
                }
        }
    };

    gload(0);
    sstore();
    __syncthreads();

    for (int kb = 0; kb < DM / KC; kb++) {
        if (kb < DM / KC - 1) gload(kb + 1);
        compute();
        __syncthreads();
        if (kb < DM / KC - 1) {
            sstore();
            __syncthreads();
        }
    }

    float alpha01 = 0.f;
    if (MODE == 2) alpha01 = __ldg(alphap) * 0.1f;

    auto xform = [&](float t) -> float {
        if (MODE == 0)      return t + 0.1f * sinf(t);
        else if (MODE == 1) return t + 0.1f * cosf(t);
        else if (MODE == 2) return t + alpha01 * tanhf(t);
        return t;
    };

#pragma unroll
    for (int tm = 0; tm < 4; tm++)
#pragma unroll
        for (int tn = 0; tn < 4; tn++) {
            const int row = m0 + (warpM << 6) + (tm << 4) + (lane >> 2);
            const int col = n0 + (warpN << 5) + (tn << 3) + ((lane & 3) << 1);
#pragma unroll
            for (int half = 0; half < 2; half++) {
                const int r = row + (half << 3);
                float2 v;
                v.x = xform(c[tm][tn][half * 2 + 0]);
                v.y = xform(c[tm][tn][half * 2 + 1]);
                size_t dst;
                if (MODE == 3) {
                    dst = (size_t)r * DM + col;
                } else {
                    const int b = r >> 11, s = r & 2047;
                    const int h = col >> 6, d = col & 63;
                    dst = (((size_t)((b << 4) + h)) << 17) + ((size_t)s << 6) + d;
                }
                *(float2*)(C + dst) = v;
            }
        }
}

// ---------------------------------------------------------------------------
// mma.sync tf32 flash attention.
// Block: 128 threads (4 warps), 64 q-rows, key tiles of 64, 32 iterations.
// Warp w owns q rows [16w, 16w+16). Q frags (x0.125, hi/lo) live in registers.
// Kd: K tile stored d-major [d][key] (= col-major B for QK); reused for P.
// Vs: V tile stored natively [key][d] (= col-major B for PV).
// 3xTF32 throughout; softmax exp via FMA-pipe polynomial (no MUFU).
// ---------------------------------------------------------------------------
#define PSTRIDE 72

__global__ __launch_bounds__(128)
void attn_mma()
{
    __shared__ float Kd[64][PSTRIDE];   // K^T tile, then P tile [q][key]
    __shared__ float Vs[64][PSTRIDE];   // V tile [key][d]

    const int tid  = threadIdx.x;
    const int lane = tid & 31;
    const int w    = tid >> 5;          // warp 0..3
    const int qb   = blockIdx.x;        // 0..31
    const int bh   = blockIdx.y;        // 0..63

    const int lr = lane >> 2;           // frag row 0..7
    const int lc = lane & 3;            // frag col 0..3

    const float* __restrict__ Qp = g_Q + ((size_t)bh << 17);
    const float* __restrict__ Kp = g_K + ((size_t)bh << 17);
    const float* __restrict__ Vp = g_V + ((size_t)bh << 17);

    // ---- Q fragments: rows (qb*64 + 16w + lr) and (+8), cols 8ks + lc (+4) ----
    uint32_t qhi[8][4], qlo[8][4];
    {
        const int q0 = (qb << 6) + (w << 4) + lr;
        const float* r0 = Qp + ((size_t)q0 << 6);
        const float* r8 = r0 + (8 << 6);
#pragma unroll
        for (int ks = 0; ks < 8; ks++) {
            const int c0 = (ks << 3) + lc;
            float v[4];
            v[0] = r0[c0]     * 0.125f;
            v[1] = r8[c0]     * 0.125f;
            v[2] = r0[c0 + 4] * 0.125f;
            v[3] = r8[c0 + 4] * 0.125f;
#pragma unroll
            for (int j = 0; j < 4; j++) {
                qhi[ks][j] = f2tf32(v[j]);
                qlo[ks][j] = f2tf32(v[j] - __uint_as_float(qhi[ks][j]));
            }
        }
    }

    float o[8][4];
#pragma unroll
    for (int i = 0; i < 8; i++)
#pragma unroll
        for (int j = 0; j < 4; j++) o[i][j] = 0.f;
    float m0v = -1e30f, m1v = -1e30f;   // running max for rows lr, lr+8
    float l0 = 0.f, l1 = 0.f;

    for (int kb = 0; kb < 32; kb++) {
        __syncthreads();    // prev iter's P/V reads done; buffers reusable

        // ---- load K tile transposed: Kd[d][key]; conflict-free STS ----
        {
            const int key = tid & 63;
            const int dbase = (tid >> 6) << 5;          // 0 or 32
            const float* kg = Kp + (((size_t)(kb << 6) + key) << 6) + dbase;
#pragma unroll
            for (int j = 0; j < 8; j++) {
                float4 v = *(const float4*)(kg + (j << 2));
                Kd[dbase + (j << 2) + 0][key] = v.x;
                Kd[dbase + (j << 2) + 1][key] = v.y;
                Kd[dbase + (j << 2) + 2][key] = v.z;
                Kd[dbase + (j << 2) + 3][key] = v.w;
            }
        }
        // ---- load V tile natively: Vs[key][d] ----
        {
            const int key = tid >> 1;
            const int dbase = (tid & 1) << 5;
            const float* vg = Vp + (((size_t)(kb << 6) + key) << 6) + dbase;
#pragma unroll
            for (int j = 0; j < 8; j++)
                *(float4*)(&Vs[key][dbase + (j << 2)]) = *(const float4*)(vg + (j << 2));
        }
        __syncthreads();

        // ---- S = (Q/8) @ K^T : 8 n-tiles of 8 keys ----
        float s[8][4];
#pragma unroll
        for (int nt = 0; nt < 8; nt++)
#pragma unroll
            for (int j = 0; j < 4; j++) s[nt][j] = 0.f;

#pragma unroll
        for (int ks = 0; ks < 8; ks++) {
#pragma unroll
            for (int nt = 0; nt < 8; nt++) {
                const float b0 = Kd[(ks << 3) + lc]    [(nt << 3) + lr];
                const float b1 = Kd[(ks << 3) + 4 + lc][(nt << 3) + lr];
                uint32_t bh2[2], bl2[2];
                bh2[0] = f2tf32(b0); bl2[0] = f2tf32(b0 - __uint_as_float(bh2[0]));
                bh2[1] = f2tf32(b1); bl2[1] = f2tf32(b1 - __uint_as_float(bh2[1]));
                mma8(s[nt], qhi[ks], bh2);
                mma8(s[nt], qhi[ks], bl2);
                mma8(s[nt], qlo[ks], bh2);
            }
        }

        // ---- online softmax (rows lr and lr+8; quad = 4 lanes per row) ----
        float rmax0 = -1e30f, rmax1 = -1e30f;
#pragma unroll
        for (int nt = 0; nt < 8; nt++) {
            rmax0 = fmaxf(rmax0, fmaxf(s[nt][0], s[nt][1]));
            rmax1 = fmaxf(rmax1, fmaxf(s[nt][2], s[nt][3]));
        }
        rmax0 = fmaxf(rmax0, __shfl_xor_sync(0xffffffffu, rmax0, 1));
        rmax0 = fmaxf(rmax0, __shfl_xor_sync(0xffffffffu, rmax0, 2));
        rmax1 = fmaxf(rmax1, __shfl_xor_sync(0xffffffffu, rmax1, 1));
        rmax1 = fmaxf(rmax1, __shfl_xor_sync(0xffffffffu, rmax1, 2));

        const float mn0 = fmaxf(m0v, rmax0);
        const float mn1 = fmaxf(m1v, rmax1);
        const float sc0 = expf_poly(m0v - mn0);
        const float sc1 = expf_poly(m1v - mn1);
        m0v = mn0; m1v = mn1;

        float ps0 = 0.f, ps1 = 0.f;
#pragma unroll
        for (int nt = 0; nt < 8; nt++) {
            s[nt][0] = expf_poly(s[nt][0] - mn0);
            s[nt][1] = expf_poly(s[nt][1] - mn0);
            s[nt][2] = expf_poly(s[nt][2] - mn1);
            s[nt][3] = expf_poly(s[nt][3] - mn1);
            ps0 += s[nt][0] + s[nt][1];
            ps1 += s[nt][2] + s[nt][3];
        }
        ps0 += __shfl_xor_sync(0xffffffffu, ps0, 1);
        ps0 += __shfl_xor_sync(0xffffffffu, ps0, 2);
        ps1 += __shfl_xor_sync(0xffffffffu, ps1, 1);
        ps1 += __shfl_xor_sync(0xffffffffu, ps1, 2);
        l0 = l0 * sc0 + ps0;
        l1 = l1 * sc1 + ps1;
#pragma unroll
        for (int nt = 0; nt < 8; nt++) {
            o[nt][0] *= sc0; o[nt][1] *= sc0;
            o[nt][2] *= sc1; o[nt][3] *= sc1;
        }

        __syncthreads();    // all warps done reading Kd (QK) -> reuse as P

        // ---- store P [q][key] (warp-local rows) ----
        {
            const int r0 = (w << 4) + lr;
#pragma unroll
            for (int nt = 0; nt < 8; nt++) {
                *(float2*)(&Kd[r0]    [(nt << 3) + (lc << 1)]) = make_float2(s[nt][0], s[nt][1]);
                *(float2*)(&Kd[r0 + 8][(nt << 3) + (lc << 1)]) = make_float2(s[nt][2], s[nt][3]);
            }
        }
        __syncwarp();

        // ---- O += P @ V ----
#pragma unroll
        for (int kc = 0; kc < 8; kc++) {
            const int r0 = (w << 4) + lr;
            float a[4];
            a[0] = Kd[r0]    [(kc << 3) + lc];
            a[1] = Kd[r0 + 8][(kc << 3) + lc];
            a[2] = Kd[r0]    [(kc << 3) + 4 + lc];
            a[3] = Kd[r0 + 8][(kc << 3) + 4 + lc];
            uint32_t phi[4], plo[4];
#pragma unroll
            for (int j = 0; j < 4; j++) {
                phi[j] = f2tf32(a[j]);
                plo[j] = f2tf32(a[j] - __uint_as_float(phi[j]));
            }
#pragma unroll
            for (int nt = 0; nt < 8; nt++) {
                const float b0 = Vs[(kc << 3) + lc]    [(nt << 3) + lr];
                const float b1 = Vs[(kc << 3) + 4 + lc][(nt << 3) + lr];
                uint32_t bh2[2], bl2[2];
                bh2[0] = f2tf32(b0); bl2[0] = f2tf32(b0 - __uint_as_float(bh2[0]));
                bh2[1] = f2tf32(b1); bl2[1] = f2tf32(b1 - __uint_as_float(bh2[1]));
                mma8(o[nt], phi, bh2);
                mma8(o[nt], phi, bl2);
                mma8(o[nt], plo, bh2);
            }
        }
    }

    // ---- finalize: O /= l, write to g_O [B,S,D] ----
    const float inv0 = 1.0f / l0;
    const float inv1 = 1.0f / l1;
    const int b = bh >> 4, h = bh & 15;
    const int s0 = (qb << 6) + (w << 4) + lr;
#pragma unroll
    for (int nt = 0; nt < 8; nt++) {
        const int col = (h << 6) + (nt << 3) + (lc << 1);
        *(float2*)(g_O + (((size_t)((b << 11) + s0)) << 10) + col) =
            make_float2(o[nt][0] * inv0, o[nt][1] * inv0);
        *(float2*)(g_O + (((size_t)((b << 11) + s0 + 8)) << 10) + col) =
            make_float2(o[nt][2] * inv1, o[nt][3] * inv1);
    }
}

// ---------------------------------------------------------------------------
extern "C" void kernel_launch(void* const* d_in, const int* in_sizes, int n_in,
                              void* d_out, int out_size)
{
    const float* x  = (const float*)d_in[0];
    const float* Wq = (const float*)d_in[1];
    const float* Wk = (const float*)d_in[2];
    const float* Wv = (const float*)d_in[3];
    const float* Wo = (const float*)d_in[4];
    const float* al = (const float*)d_in[5];
    float* out = (float*)d_out;

    float *qp, *kp, *vp, *op;
    cudaGetSymbolAddress((void**)&qp, g_Q);
    cudaGetSymbolAddress((void**)&kp, g_K);
    cudaGetSymbolAddress((void**)&vp, g_V);
    cudaGetSymbolAddress((void**)&op, g_O);

    dim3 ggrid(DM / 128, MROWS / 128);   // 8 x 64
    gemm_mma<0><<<ggrid, 256>>>(x, Wq, qp, nullptr);
    gemm_mma<1><<<ggrid, 256>>>(x, Wk, kp, nullptr);
    gemm_mma<2><<<ggrid, 256>>>(x, Wv, vp, al);

    attn_mma<<<dim3(SLEN / 64, (MROWS / SLEN) * NHEAD), 128>>>();  // 32 x 64

    gemm_mma<3><<<ggrid, 256>>>(op, Wo, out, nullptr);
}